// round 1
// baseline (speedup 1.0000x reference)
#include <cuda_runtime.h>

#define N_NODES 8192
#define D_DIM   512
#define P_PERS  16
#define K_TOT   (P_PERS * D_DIM)   /* 8192 */
#define TOPK    64
#define EPSILON 0.1f

#define BM 128
#define BN 128
#define BK 8
#define TM 8
#define TN 8

#define CAND_CAP 4096

// Scratch: normalized, perspective-stacked feature matrix Y [N_NODES, K_TOT]
// adj = Y * Y^T  (the 1/16 perspective mean is folded in as 1/4 per factor).
__device__ float g_Y[(size_t)N_NODES * K_TOT];

// ---------------------------------------------------------------------------
// Kernel 1: build Y.  One block per node row.
// Y[n, p*512+d] = x[n,d]*w[p,d] * (0.25 / max(||x[n]∘w[p]||, 1e-12))
// ---------------------------------------------------------------------------
__global__ __launch_bounds__(256) void build_y_kernel(
    const float* __restrict__ x, const float* __restrict__ w)
{
    const int n = blockIdx.x;
    __shared__ float sx[D_DIM];
    __shared__ float red[8];

    const float* xr = x + (size_t)n * D_DIM;
    for (int d = threadIdx.x; d < D_DIM; d += blockDim.x) sx[d] = xr[d];
    __syncthreads();

    for (int p = 0; p < P_PERS; ++p) {
        const float* wp = w + p * D_DIM;
        float s = 0.f;
        for (int d = threadIdx.x; d < D_DIM; d += blockDim.x) {
            float v = sx[d] * wp[d];
            s += v * v;
        }
        // block reduction (256 threads -> 8 warps)
        #pragma unroll
        for (int o = 16; o > 0; o >>= 1) s += __shfl_xor_sync(0xFFFFFFFFu, s, o);
        if ((threadIdx.x & 31) == 0) red[threadIdx.x >> 5] = s;
        __syncthreads();
        float tot;
        if (threadIdx.x < 32) {
            float t = (threadIdx.x < 8) ? red[threadIdx.x] : 0.f;
            #pragma unroll
            for (int o = 4; o > 0; o >>= 1) t += __shfl_xor_sync(0xFFFFFFFFu, t, o);
            if (threadIdx.x == 0) red[0] = t;
        }
        __syncthreads();
        tot = red[0];

        const float inv = 0.25f / fmaxf(sqrtf(tot), 1e-12f);
        float* yout = g_Y + (size_t)n * K_TOT + (size_t)p * D_DIM;
        for (int d = threadIdx.x; d < D_DIM; d += blockDim.x)
            yout[d] = sx[d] * wp[d] * inv;
        __syncthreads();   // red[] reused next p
    }
}

// ---------------------------------------------------------------------------
// Kernel 2: fp32 SYRK  C = Y * Y^T, upper-triangular blocks only, mirrored.
// Classic 128x128x8 smem-tiled sgemm, 256 threads, 8x8 per-thread microtile.
// ---------------------------------------------------------------------------
__global__ __launch_bounds__(256) void syrk_kernel(float* __restrict__ C)
{
    const int bi = blockIdx.y;   // row block
    const int bj = blockIdx.x;   // col block
    if (bj < bi) return;         // symmetry: only upper triangle

    __shared__ float As[BK][BM];
    __shared__ float Bs[BK][BN];

    const int tid  = threadIdx.x;
    const int tx   = tid & 15;          // 0..15  (N direction)
    const int ty   = tid >> 4;          // 0..15  (M direction)
    const int lrow = tid >> 1;          // 0..127 load row
    const int lk   = (tid & 1) * 4;     // 0 or 4

    const float* Aptr = g_Y + ((size_t)bi * BM + lrow) * K_TOT + lk;
    const float* Bptr = g_Y + ((size_t)bj * BN + lrow) * K_TOT + lk;

    float acc[TM][TN];
    #pragma unroll
    for (int i = 0; i < TM; ++i)
        #pragma unroll
        for (int j = 0; j < TN; ++j) acc[i][j] = 0.f;

    for (int k0 = 0; k0 < K_TOT; k0 += BK) {
        const float4 a4 = *(const float4*)(Aptr + k0);
        const float4 b4 = *(const float4*)(Bptr + k0);
        As[lk + 0][lrow] = a4.x; As[lk + 1][lrow] = a4.y;
        As[lk + 2][lrow] = a4.z; As[lk + 3][lrow] = a4.w;
        Bs[lk + 0][lrow] = b4.x; Bs[lk + 1][lrow] = b4.y;
        Bs[lk + 2][lrow] = b4.z; Bs[lk + 3][lrow] = b4.w;
        __syncthreads();

        #pragma unroll
        for (int kk = 0; kk < BK; ++kk) {
            float af[TM], bf[TN];
            const float4 af0 = *(const float4*)&As[kk][ty * TM];
            const float4 af1 = *(const float4*)&As[kk][ty * TM + 4];
            const float4 bf0 = *(const float4*)&Bs[kk][tx * TN];
            const float4 bf1 = *(const float4*)&Bs[kk][tx * TN + 4];
            af[0]=af0.x; af[1]=af0.y; af[2]=af0.z; af[3]=af0.w;
            af[4]=af1.x; af[5]=af1.y; af[6]=af1.z; af[7]=af1.w;
            bf[0]=bf0.x; bf[1]=bf0.y; bf[2]=bf0.z; bf[3]=bf0.w;
            bf[4]=bf1.x; bf[5]=bf1.y; bf[6]=bf1.z; bf[7]=bf1.w;
            #pragma unroll
            for (int i = 0; i < TM; ++i)
                #pragma unroll
                for (int j = 0; j < TN; ++j)
                    acc[i][j] = fmaf(af[i], bf[j], acc[i][j]);
        }
        __syncthreads();
    }

    const size_t m0 = (size_t)bi * BM;
    const size_t n0 = (size_t)bj * BN;

    // normal tile store: C[m0+ty*8+i][n0+tx*8 .. +7]
    #pragma unroll
    for (int i = 0; i < TM; ++i) {
        float* crow = C + (m0 + ty * TM + i) * N_NODES + n0 + tx * TN;
        float4 v0 = make_float4(acc[i][0], acc[i][1], acc[i][2], acc[i][3]);
        float4 v1 = make_float4(acc[i][4], acc[i][5], acc[i][6], acc[i][7]);
        *(float4*)(crow)     = v0;
        *(float4*)(crow + 4) = v1;
    }

    // mirrored store (skip on diagonal block: already fully covered)
    if (bj > bi) {
        #pragma unroll
        for (int j = 0; j < TN; ++j) {
            float* crow = C + (n0 + tx * TN + j) * N_NODES + m0 + ty * TM;
            float4 v0 = make_float4(acc[0][j], acc[1][j], acc[2][j], acc[3][j]);
            float4 v1 = make_float4(acc[4][j], acc[5][j], acc[6][j], acc[7][j]);
            *(float4*)(crow)     = v0;
            *(float4*)(crow + 4) = v1;
        }
    }
}

// ---------------------------------------------------------------------------
// Kernel 3: per-row epsilon filter + top-64 select + scatter (in place).
// One block per row. Candidates (>0.1, ~136 expected) compacted into smem;
// rank by (value desc, index asc) matches jax.lax.top_k tie-breaking.
// ---------------------------------------------------------------------------
__global__ __launch_bounds__(256) void topk_kernel(float* __restrict__ C)
{
    const int row = blockIdx.x;
    float* r = C + (size_t)row * N_NODES;

    __shared__ float sval[CAND_CAP];
    __shared__ int   sidx[CAND_CAP];
    __shared__ int   scnt;
    if (threadIdx.x == 0) scnt = 0;
    __syncthreads();

    for (int j = threadIdx.x; j < N_NODES; j += blockDim.x) {
        const float v = r[j];
        if (v > EPSILON) {
            const int p = atomicAdd(&scnt, 1);
            if (p < CAND_CAP) { sval[p] = v; sidx[p] = j; }
        }
    }
    __syncthreads();
    const int cnt = min(scnt, CAND_CAP);

    // zero the whole row, then scatter winners back
    for (int j = threadIdx.x; j < N_NODES; j += blockDim.x) r[j] = 0.f;
    __syncthreads();

    for (int i = threadIdx.x; i < cnt; i += blockDim.x) {
        const float vi = sval[i];
        const int   ii = sidx[i];
        int rank = 0;
        for (int j = 0; j < cnt; ++j) {
            const float vj = sval[j];
            rank += (vj > vi) || (vj == vi && sidx[j] < ii);
        }
        if (rank < TOPK) r[ii] = vi;
    }
}

// ---------------------------------------------------------------------------
extern "C" void kernel_launch(void* const* d_in, const int* in_sizes, int n_in,
                              void* d_out, int out_size)
{
    const float* x = (const float*)d_in[0];
    const float* w = (const float*)d_in[1];
    // defensive: identify operands by size (weight is 16*512 = 8192 elems)
    if (n_in >= 2 && in_sizes[0] == P_PERS * D_DIM) {
        const float* t = x; x = w; w = t;
    }
    float* C = (float*)d_out;

    build_y_kernel<<<N_NODES, 256>>>(x, w);
    dim3 grid(N_NODES / BN, N_NODES / BM);
    syrk_kernel<<<grid, 256>>>(C);
    topk_kernel<<<N_NODES, 256>>>(C);
}

// round 4
// speedup vs baseline: 2.2037x; 2.2037x over previous
#include <cuda_runtime.h>
#include <cuda_bf16.h>
#include <cstdint>

#define NN      8192
#define DD      512
#define PP      16
#define KT      8192
#define TOPK    64
#define EPSILON 0.1f
#define TAU     1e-4f

#define KSTG    64                  // k-features per pipeline stage
#define NSTG    (KT / KSTG)         // 128 stages
#define STAGES  3
#define SCAP    1024
#define RCAP    64

// bf16 hi/lo split of normalized Y, row-major [NN][KT]; fp32 copy for rescue
__device__ __align__(128) __nv_bfloat16 g_Yh[(size_t)NN * KT];
__device__ __align__(128) __nv_bfloat16 g_Yl[(size_t)NN * KT];
__device__ __align__(128) float         g_Yf[(size_t)NN * KT];

__device__ __forceinline__ uint32_t sw128(uint32_t off) {
    return off ^ ((off >> 3) & 0x70);
}
__device__ __forceinline__ uint32_t smem_u32(const void* p) {
    return (uint32_t)__cvta_generic_to_shared(p);
}
__device__ __forceinline__ void cp16(uint32_t dst, const void* src) {
    asm volatile("cp.async.cg.shared.global [%0], [%1], 16;" :: "r"(dst), "l"(src));
}
__device__ __forceinline__ void cp_commit() {
    asm volatile("cp.async.commit_group;" ::: "memory");
}
__device__ __forceinline__ void cp_wait1() {
    asm volatile("cp.async.wait_group 1;" ::: "memory");
}
__device__ __forceinline__ void cp_wait0() {
    asm volatile("cp.async.wait_group 0;" ::: "memory");
}
__device__ __forceinline__ void ldm_x4(uint32_t* r, uint32_t addr) {
    asm volatile("ldmatrix.sync.aligned.m8n8.x4.shared.b16 {%0,%1,%2,%3}, [%4];"
                 : "=r"(r[0]), "=r"(r[1]), "=r"(r[2]), "=r"(r[3]) : "r"(addr));
}
__device__ __forceinline__ void ldm_x2(uint32_t* r, uint32_t addr) {
    asm volatile("ldmatrix.sync.aligned.m8n8.x2.shared.b16 {%0,%1}, [%2];"
                 : "=r"(r[0]), "=r"(r[1]) : "r"(addr));
}
__device__ __forceinline__ void mma16816(float* c, const uint32_t* a, const uint32_t* b) {
    asm volatile(
        "mma.sync.aligned.m16n8k16.row.col.f32.bf16.bf16.f32 "
        "{%0,%1,%2,%3}, {%4,%5,%6,%7}, {%8,%9}, {%0,%1,%2,%3};"
        : "+f"(c[0]), "+f"(c[1]), "+f"(c[2]), "+f"(c[3])
        : "r"(a[0]), "r"(a[1]), "r"(a[2]), "r"(a[3]), "r"(b[0]), "r"(b[1]));
}

#define MAT_BYTES   16384
#define STG_BYTES   65536
#define SMEM_TOTAL  (STAGES * STG_BYTES + 1024)

// ---------------------------------------------------------------------------
// Kernel 1: build bf16 hi/lo split + fp32 copy of Y.
// Y[n, p*512+d] = x[n,d]*w[p,d] * (0.25 / max(||x[n].*w[p]||, 1e-12))
// ---------------------------------------------------------------------------
__global__ __launch_bounds__(256) void build_y_kernel(
    const float* __restrict__ x, const float* __restrict__ w)
{
    const int n = blockIdx.x;
    __shared__ float sx[DD];
    __shared__ float red[8];

    const float* xr = x + (size_t)n * DD;
    for (int d = threadIdx.x; d < DD; d += 256) sx[d] = xr[d];
    __syncthreads();

    for (int p = 0; p < PP; ++p) {
        const float* wp = w + p * DD;
        float s = 0.f;
        for (int d = threadIdx.x; d < DD; d += 256) {
            float v = sx[d] * wp[d];
            s += v * v;
        }
        #pragma unroll
        for (int o = 16; o > 0; o >>= 1) s += __shfl_xor_sync(0xFFFFFFFFu, s, o);
        if ((threadIdx.x & 31) == 0) red[threadIdx.x >> 5] = s;
        __syncthreads();
        if (threadIdx.x < 32) {
            float t = (threadIdx.x < 8) ? red[threadIdx.x] : 0.f;
            #pragma unroll
            for (int o = 4; o > 0; o >>= 1) t += __shfl_xor_sync(0xFFFFFFFFu, t, o);
            if (threadIdx.x == 0) red[0] = t;
        }
        __syncthreads();
        const float inv = 0.25f / fmaxf(sqrtf(red[0]), 1e-12f);

        const int d0 = 2 * threadIdx.x;                 // 0..510
        const float v0 = sx[d0]     * wp[d0]     * inv;
        const float v1 = sx[d0 + 1] * wp[d0 + 1] * inv;
        const __nv_bfloat16 h0 = __float2bfloat16(v0);
        const __nv_bfloat16 h1 = __float2bfloat16(v1);
        const __nv_bfloat16 l0 = __float2bfloat16(v0 - __bfloat162float(h0));
        const __nv_bfloat16 l1 = __float2bfloat16(v1 - __bfloat162float(h1));

        const size_t base = (size_t)n * KT + (size_t)p * DD + d0;
        __nv_bfloat162 hv; hv.x = h0; hv.y = h1;
        __nv_bfloat162 lv; lv.x = l0; lv.y = l1;
        *(__nv_bfloat162*)(g_Yh + base) = hv;
        *(__nv_bfloat162*)(g_Yl + base) = lv;
        *(float2*)(g_Yf + base) = make_float2(v0, v1);
        __syncthreads();
    }
}

// ---------------------------------------------------------------------------
// Kernel 2: tensor-core SYRK via mma.sync bf16, 3-term split (hh+hl+lh).
// 128x128 tile per CTA, upper-triangle tiles, mirrored stores.
// ---------------------------------------------------------------------------
__global__ __launch_bounds__(256, 1) void syrk_mma_kernel(float* __restrict__ C)
{
    const int bi = blockIdx.y;
    const int bj = blockIdx.x;
    if (bj < bi) return;

    extern __shared__ char smem_raw[];
    const uint32_t sbase = (smem_u32(smem_raw) + 1023) & ~1023u;

    const int tid  = threadIdx.x;
    const int lane = tid & 31;
    const int wid  = tid >> 5;
    const int wm   = wid & 1;        // 2 warps in M -> warp tile M=64
    const int wn   = wid >> 1;       // 4 warps in N -> warp tile N=32

    const char* gh = (const char*)g_Yh;
    const char* gl = (const char*)g_Yl;
    auto load_stage = [&](int s, int buf) {
        const uint32_t dbase = sbase + buf * STG_BYTES;
        const size_t arow0 = (size_t)bi * 128;
        const size_t brow0 = (size_t)bj * 128;
        const size_t koff  = (size_t)s * KSTG * 2;
        #pragma unroll
        for (int i = 0; i < 16; ++i) {
            const int c   = tid + 256 * i;
            const int mat = c >> 10;
            const int idx = c & 1023;
            const int row = idx >> 3;
            const int kch = idx & 7;
            const size_t grow = ((mat & 2) ? brow0 : arow0) + row;
            const char* src = ((mat & 1) ? gl : gh)
                            + grow * (KT * 2) + koff + kch * 16;
            const uint32_t dst = dbase + mat * MAT_BYTES
                               + sw128((uint32_t)(row * 128 + kch * 16));
            cp16(dst, src);
        }
        cp_commit();
    };

    load_stage(0, 0);
    load_stage(1, 1);

    float acc[4][4][4];
    #pragma unroll
    for (int a = 0; a < 4; ++a)
        #pragma unroll
        for (int b = 0; b < 4; ++b)
            #pragma unroll
            for (int r = 0; r < 4; ++r) acc[a][b][r] = 0.f;

    const int a_row = wm * 64 + (lane & 15);
    const int a_col = (lane >> 4) * 8;
    const int l16   = lane & 15;
    const int b_row = wn * 32 + (l16 & 7);
    const int b_col = (l16 >> 3) * 8;

    for (int s = 0; s < NSTG; ++s) {
        if (s == NSTG - 1) cp_wait0(); else cp_wait1();
        __syncthreads();
        if (s + 2 < NSTG) load_stage(s + 2, (s + 2) % STAGES);

        const uint32_t bufb = sbase + (s % STAGES) * STG_BYTES;
        const uint32_t aHi = bufb;
        const uint32_t aLo = bufb + MAT_BYTES;
        const uint32_t bHi = bufb + 2 * MAT_BYTES;
        const uint32_t bLo = bufb + 3 * MAT_BYTES;

        #pragma unroll
        for (int ks = 0; ks < 4; ++ks) {
            uint32_t ah[4][4], al[4][4], bh[4][2], bl[4][2];
            #pragma unroll
            for (int mf = 0; mf < 4; ++mf) {
                const uint32_t off = sw128((uint32_t)(
                    (a_row + mf * 16) * 128 + (a_col + ks * 16) * 2));
                ldm_x4(ah[mf], aHi + off);
                ldm_x4(al[mf], aLo + off);
            }
            #pragma unroll
            for (int nf = 0; nf < 4; ++nf) {
                const uint32_t off = sw128((uint32_t)(
                    (b_row + nf * 8) * 128 + (b_col + ks * 16) * 2));
                ldm_x2(bh[nf], bHi + off);
                ldm_x2(bl[nf], bLo + off);
            }
            #pragma unroll
            for (int mf = 0; mf < 4; ++mf)
                #pragma unroll
                for (int nf = 0; nf < 4; ++nf) {
                    mma16816(acc[mf][nf], ah[mf], bh[nf]);   // hi*hi
                    mma16816(acc[mf][nf], ah[mf], bl[nf]);   // hi*lo
                    mma16816(acc[mf][nf], al[mf], bh[nf]);   // lo*hi
                }
        }
        __syncthreads();
    }

    const size_t m0 = (size_t)bi * 128 + wm * 64;
    const size_t n0 = (size_t)bj * 128 + wn * 32;
    const int cr = lane >> 2;
    const int cc = (lane & 3) * 2;

    #pragma unroll
    for (int mf = 0; mf < 4; ++mf)
        #pragma unroll
        for (int nf = 0; nf < 4; ++nf) {
            const size_t r0 = m0 + mf * 16 + cr;
            const size_t r1 = r0 + 8;
            const size_t c0 = n0 + nf * 8 + cc;
            float2 v01 = make_float2(acc[mf][nf][0], acc[mf][nf][1]);
            float2 v23 = make_float2(acc[mf][nf][2], acc[mf][nf][3]);
            *(float2*)(C + r0 * NN + c0) = v01;
            *(float2*)(C + r1 * NN + c0) = v23;
            if (bj > bi) {
                C[(c0    ) * NN + r0] = acc[mf][nf][0];
                C[(c0 + 1) * NN + r0] = acc[mf][nf][1];
                C[(c0    ) * NN + r1] = acc[mf][nf][2];
                C[(c0 + 1) * NN + r1] = acc[mf][nf][3];
            }
        }
}

// ---------------------------------------------------------------------------
// Kernel 3: epsilon + top-64 with exact fp32 rescue at the decision boundary.
// Candidates within TAU of the (noisy) 64th value or of EPSILON get their dot
// product recomputed with the exact round-1 summation order (sequential k,
// single fp32 accumulator) so the kept/dropped decision is GEMM-noise-free.
// ---------------------------------------------------------------------------
__global__ __launch_bounds__(256) void topk_kernel(float* __restrict__ C)
{
    const int row = blockIdx.x;
    float* r = C + (size_t)row * NN;
    const int tid = threadIdx.x;

    __shared__ float sval[SCAP];
    __shared__ int   sidx[SCAP];
    __shared__ float sex[RCAP];
    __shared__ int   rlist[RCAP];
    __shared__ int   scnt, rcnt;
    __shared__ float sv64;
    extern __shared__ float sYr[];     // 8192 floats (32KB)

    if (tid == 0) { scnt = 0; rcnt = 0; sv64 = -1e30f; }
    __syncthreads();

    // 1. collect candidate pool (with TAU slack below epsilon)
    for (int j = tid; j < NN; j += 256) {
        const float v = r[j];
        if (v > EPSILON - TAU) {
            const int p = atomicAdd(&scnt, 1);
            if (p < SCAP) { sval[p] = v; sidx[p] = j; }
        }
    }
    __syncthreads();
    const int cnt = min(scnt, SCAP);

    // 2. zero the row
    for (int j = tid; j < NN; j += 256) r[j] = 0.f;

    // 3. noisy 64th value among epsilon-passing candidates
    for (int i = tid; i < cnt; i += 256) {
        const float vi = sval[i];
        if (vi <= EPSILON) continue;
        const int ii = sidx[i];
        int rank = 0;
        for (int j = 0; j < cnt; ++j) {
            const float vj = sval[j];
            if (vj <= EPSILON) continue;
            rank += (vj > vi) || (vj == vi && sidx[j] < ii);
        }
        if (rank == TOPK - 1) sv64 = vi;
    }
    __syncthreads();
    const float v64 = sv64;

    // 4. rescue set: ambiguous near the top-k cutoff or the epsilon threshold
    for (int i = tid; i < cnt; i += 256) {
        const float vi = sval[i];
        if (fabsf(vi - v64) <= TAU || fabsf(vi - EPSILON) <= TAU) {
            const int p = atomicAdd(&rcnt, 1);
            if (p < RCAP) rlist[p] = i;
        }
    }
    __syncthreads();
    const int rc = min(rcnt, RCAP);

    if (rc > 0) {
        const float* Yr = g_Yf + (size_t)row * KT;
        for (int j = tid; j < KT; j += 256) sYr[j] = Yr[j];
        __syncthreads();
        if (tid < rc) {
            const int i = rlist[tid];
            const int c = sidx[i];
            const float4* bp = (const float4*)(g_Yf + (size_t)c * KT);
            const float4* ap = (const float4*)sYr;
            float acc = 0.f;
            for (int k = 0; k < KT / 4; ++k) {
                const float4 a = ap[k];
                const float4 b = __ldg(bp + k);
                acc = fmaf(a.x, b.x, acc);
                acc = fmaf(a.y, b.y, acc);
                acc = fmaf(a.z, b.z, acc);
                acc = fmaf(a.w, b.w, acc);
            }
            sex[tid] = acc;
        }
        __syncthreads();
        if (tid < rc) sval[rlist[tid]] = sex[tid];
        __syncthreads();
    }

    // 5. final rank + scatter (exact values decide at the boundary)
    for (int i = tid; i < cnt; i += 256) {
        const float vi = sval[i];
        if (vi <= EPSILON) continue;
        const int ii = sidx[i];
        int rank = 0;
        for (int j = 0; j < cnt; ++j) {
            const float vj = sval[j];
            if (vj <= EPSILON) continue;
            rank += (vj > vi) || (vj == vi && sidx[j] < ii);
        }
        if (rank < TOPK) r[ii] = vi;
    }
}

// ---------------------------------------------------------------------------
extern "C" void kernel_launch(void* const* d_in, const int* in_sizes, int n_in,
                              void* d_out, int out_size)
{
    const float* x = (const float*)d_in[0];
    const float* w = (const float*)d_in[1];
    if (n_in >= 2 && in_sizes[0] == PP * DD) { const float* t = x; x = w; w = t; }
    float* C = (float*)d_out;

    cudaFuncSetAttribute(syrk_mma_kernel,
                         cudaFuncAttributeMaxDynamicSharedMemorySize, SMEM_TOTAL);

    build_y_kernel<<<NN, 256>>>(x, w);
    dim3 grid(64, 64);
    syrk_mma_kernel<<<grid, 256, SMEM_TOTAL>>>(C);
    topk_kernel<<<NN, 256, KT * sizeof(float)>>>(C);
}

// round 5
// speedup vs baseline: 3.3054x; 1.4999x over previous
#include <cuda_runtime.h>
#include <cuda_fp16.h>
#include <cstdint>

#define NN      8192
#define DD      512
#define PP      16
#define KT      8192
#define TOPK    64
#define EPSILON 0.1f
#define TAU     2.5e-4f

#define KSTG    64
#define NSTG    (KT / KSTG)         // 128
#define STAGES  4
#define SCAP    1024
#define RCAP    128

// fp16 plane for tensor GEMM; fp32 plane for exact boundary rescue
__device__ __align__(128) __half g_Yh[(size_t)NN * KT];
__device__ __align__(128) float  g_Yf[(size_t)NN * KT];

__device__ __forceinline__ uint32_t sw128(uint32_t off) {
    return off ^ ((off >> 3) & 0x70);
}
__device__ __forceinline__ uint32_t smem_u32(const void* p) {
    return (uint32_t)__cvta_generic_to_shared(p);
}
__device__ __forceinline__ void cp16(uint32_t dst, const void* src) {
    asm volatile("cp.async.cg.shared.global [%0], [%1], 16;" :: "r"(dst), "l"(src));
}
__device__ __forceinline__ void cp_commit() {
    asm volatile("cp.async.commit_group;" ::: "memory");
}
__device__ __forceinline__ void cp_wait3() {
    asm volatile("cp.async.wait_group 3;" ::: "memory");
}
__device__ __forceinline__ void ldm_x4(uint32_t* r, uint32_t addr) {
    asm volatile("ldmatrix.sync.aligned.m8n8.x4.shared.b16 {%0,%1,%2,%3}, [%4];"
                 : "=r"(r[0]), "=r"(r[1]), "=r"(r[2]), "=r"(r[3]) : "r"(addr));
}
__device__ __forceinline__ void ldm_x2(uint32_t* r, uint32_t addr) {
    asm volatile("ldmatrix.sync.aligned.m8n8.x2.shared.b16 {%0,%1}, [%2];"
                 : "=r"(r[0]), "=r"(r[1]) : "r"(addr));
}
__device__ __forceinline__ void mma16816(float* c, const uint32_t* a, const uint32_t* b) {
    asm volatile(
        "mma.sync.aligned.m16n8k16.row.col.f32.f16.f16.f32 "
        "{%0,%1,%2,%3}, {%4,%5,%6,%7}, {%8,%9}, {%0,%1,%2,%3};"
        : "+f"(c[0]), "+f"(c[1]), "+f"(c[2]), "+f"(c[3])
        : "r"(a[0]), "r"(a[1]), "r"(a[2]), "r"(a[3]), "r"(b[0]), "r"(b[1]));
}

// per stage: A 128x64 fp16 (16KB) | B 256x64 fp16 (32KB)
#define A_BYTES     16384
#define STG_BYTES   49152
#define SMEM_TOTAL  (STAGES * STG_BYTES + 1024)

// ---------------------------------------------------------------------------
// Kernel 1: Y[n, p*512+d] = x[n,d]*w[p,d] * (0.25/max(||x[n].*w[p]||,1e-12))
// stored as fp16 (GEMM) + fp32 (rescue).
// ---------------------------------------------------------------------------
__global__ __launch_bounds__(256) void build_y_kernel(
    const float* __restrict__ x, const float* __restrict__ w)
{
    const int n = blockIdx.x;
    __shared__ float sx[DD];
    __shared__ float red[8];

    const float* xr = x + (size_t)n * DD;
    for (int d = threadIdx.x; d < DD; d += 256) sx[d] = xr[d];
    __syncthreads();

    for (int p = 0; p < PP; ++p) {
        const float* wp = w + p * DD;
        float s = 0.f;
        for (int d = threadIdx.x; d < DD; d += 256) {
            float v = sx[d] * wp[d];
            s += v * v;
        }
        #pragma unroll
        for (int o = 16; o > 0; o >>= 1) s += __shfl_xor_sync(0xFFFFFFFFu, s, o);
        if ((threadIdx.x & 31) == 0) red[threadIdx.x >> 5] = s;
        __syncthreads();
        if (threadIdx.x < 32) {
            float t = (threadIdx.x < 8) ? red[threadIdx.x] : 0.f;
            #pragma unroll
            for (int o = 4; o > 0; o >>= 1) t += __shfl_xor_sync(0xFFFFFFFFu, t, o);
            if (threadIdx.x == 0) red[0] = t;
        }
        __syncthreads();
        const float inv = 0.25f / fmaxf(sqrtf(red[0]), 1e-12f);

        const int d0 = 2 * threadIdx.x;
        const float v0 = sx[d0]     * wp[d0]     * inv;
        const float v1 = sx[d0 + 1] * wp[d0 + 1] * inv;

        const size_t base = (size_t)n * KT + (size_t)p * DD + d0;
        __half2 hv; hv.x = __float2half_rn(v0); hv.y = __float2half_rn(v1);
        *(__half2*)(g_Yh + base) = hv;
        *(float2*)(g_Yf + base) = make_float2(v0, v1);
        __syncthreads();
    }
}

// ---------------------------------------------------------------------------
// Kernel 2: fp16 tensor-core SYRK. 128x256 CTA tile, 64x64 warp tiles,
// 4-stage cp.async pipeline, triangle tiles + mirrored stores.
// ---------------------------------------------------------------------------
__global__ __launch_bounds__(256, 1) void syrk_mma_kernel(float* __restrict__ C)
{
    const int bi = blockIdx.y;   // 0..63  (128-row panel)
    const int bj = blockIdx.x;   // 0..31  (256-col panel)
    if (bj < (bi >> 1)) return;

    extern __shared__ char smem_raw[];
    const uint32_t sbase = (smem_u32(smem_raw) + 1023) & ~1023u;

    const int tid  = threadIdx.x;
    const int lane = tid & 31;
    const int wid  = tid >> 5;
    const int wm   = wid & 1;        // 2 warps in M (64 each)
    const int wn   = wid >> 1;       // 4 warps in N (64 each)

    auto load_stage = [&](int s, int buf) {
        const uint32_t dbase = sbase + buf * STG_BYTES;
        const size_t arow0 = (size_t)bi * 128;
        const size_t brow0 = (size_t)bj * 256;
        const int koff = s * KSTG;
        #pragma unroll
        for (int i = 0; i < 12; ++i) {
            const int c = tid + 256 * i;     // 0..3071
            if (c < 1024) {                  // A: 128 rows x 8 chunks
                const int row = c >> 3, kch = c & 7;
                cp16(dbase + sw128((uint32_t)(row * 128 + kch * 16)),
                     g_Yh + (arow0 + row) * KT + koff + kch * 8);
            } else {                         // B: 256 rows x 8 chunks
                const int idx = c - 1024;
                const int row = idx >> 3, kch = idx & 7;
                cp16(dbase + A_BYTES + sw128((uint32_t)(row * 128 + kch * 16)),
                     g_Yh + (brow0 + row) * KT + koff + kch * 8);
            }
        }
        cp_commit();
    };

    load_stage(0, 0);
    load_stage(1, 1);
    load_stage(2, 2);

    float acc[4][8][4];
    #pragma unroll
    for (int a = 0; a < 4; ++a)
        #pragma unroll
        for (int b = 0; b < 8; ++b)
            #pragma unroll
            for (int r = 0; r < 4; ++r) acc[a][b][r] = 0.f;

    const int a_row = wm * 64 + (lane & 15);
    const int a_col = (lane >> 4) * 8;
    const int l16   = lane & 15;
    const int b_rowb = wn * 64 + (l16 & 7);
    const int b_colb = (l16 >> 3) * 8;

    for (int s = 0; s < NSTG; ++s) {
        if (s + 3 < NSTG) load_stage(s + 3, (s + 3) & 3);
        else cp_commit();                     // keep group count uniform
        cp_wait3();
        __syncthreads();

        const uint32_t aB = sbase + (s & 3) * STG_BYTES;
        const uint32_t bB = aB + A_BYTES;

        #pragma unroll
        for (int ks = 0; ks < 4; ++ks) {
            uint32_t ah[4][4], bh[8][2];
            #pragma unroll
            for (int mf = 0; mf < 4; ++mf)
                ldm_x4(ah[mf], aB + sw128((uint32_t)(
                    (a_row + mf * 16) * 128 + (a_col + ks * 16) * 2)));
            #pragma unroll
            for (int nf = 0; nf < 8; ++nf)
                ldm_x2(bh[nf], bB + sw128((uint32_t)(
                    (b_rowb + nf * 8) * 128 + (b_colb + ks * 16) * 2)));
            #pragma unroll
            for (int mf = 0; mf < 4; ++mf)
                #pragma unroll
                for (int nf = 0; nf < 8; ++nf)
                    mma16816(acc[mf][nf], ah[mf], bh[nf]);
        }
        __syncthreads();
    }

    // ---- epilogue: direct (always-correct value) + guarded mirror ----
    const size_t m0 = (size_t)bi * 128 + wm * 64;
    const size_t n0 = (size_t)bj * 256 + wn * 64;
    const int cr = lane >> 2;
    const int cc = (lane & 3) * 2;

    #pragma unroll
    for (int mf = 0; mf < 4; ++mf)
        #pragma unroll
        for (int nf = 0; nf < 8; ++nf) {
            const size_t r0 = m0 + mf * 16 + cr;
            const size_t r1 = r0 + 8;
            const size_t c0 = n0 + nf * 8 + cc;
            *(float2*)(C + r0 * NN + c0) = make_float2(acc[mf][nf][0], acc[mf][nf][1]);
            *(float2*)(C + r1 * NN + c0) = make_float2(acc[mf][nf][2], acc[mf][nf][3]);
            if (c0     > r0) C[(c0    ) * NN + r0] = acc[mf][nf][0];
            if (c0 + 1 > r0) C[(c0 + 1) * NN + r0] = acc[mf][nf][1];
            if (c0     > r1) C[(c0    ) * NN + r1] = acc[mf][nf][2];
            if (c0 + 1 > r1) C[(c0 + 1) * NN + r1] = acc[mf][nf][3];
        }
}

// ---------------------------------------------------------------------------
// Kernel 3: epsilon + top-64 with exact fp32 rescue at decision boundaries.
// ---------------------------------------------------------------------------
__global__ __launch_bounds__(256) void topk_kernel(float* __restrict__ C)
{
    const int row = blockIdx.x;
    float* r = C + (size_t)row * NN;
    const int tid = threadIdx.x;

    __shared__ float sval[SCAP];
    __shared__ int   sidx[SCAP];
    __shared__ float sex[RCAP];
    __shared__ int   rlist[RCAP];
    __shared__ int   scnt, rcnt;
    __shared__ float sv64;
    extern __shared__ float sYr[];     // 8192 floats

    if (tid == 0) { scnt = 0; rcnt = 0; sv64 = -1e30f; }
    __syncthreads();

    for (int j = tid; j < NN; j += 256) {
        const float v = r[j];
        if (v > EPSILON - TAU) {
            const int p = atomicAdd(&scnt, 1);
            if (p < SCAP) { sval[p] = v; sidx[p] = j; }
        }
    }
    __syncthreads();
    const int cnt = min(scnt, SCAP);

    for (int j = tid; j < NN; j += 256) r[j] = 0.f;

    // noisy 64th value among epsilon-passing candidates
    for (int i = tid; i < cnt; i += 256) {
        const float vi = sval[i];
        if (vi <= EPSILON) continue;
        const int ii = sidx[i];
        int rank = 0;
        for (int j = 0; j < cnt; ++j) {
            const float vj = sval[j];
            if (vj <= EPSILON) continue;
            rank += (vj > vi) || (vj == vi && sidx[j] < ii);
        }
        if (rank == TOPK - 1) sv64 = vi;
    }
    __syncthreads();
    const float v64 = sv64;

    // rescue set: ambiguous near the cutoff or near epsilon
    for (int i = tid; i < cnt; i += 256) {
        const float vi = sval[i];
        if (fabsf(vi - v64) <= TAU || fabsf(vi - EPSILON) <= TAU) {
            const int p = atomicAdd(&rcnt, 1);
            if (p < RCAP) rlist[p] = i;
        }
    }
    __syncthreads();
    const int rc = min(rcnt, RCAP);

    if (rc > 0) {
        const float* Yr = g_Yf + (size_t)row * KT;
        for (int j = tid; j < KT; j += 256) sYr[j] = Yr[j];
        __syncthreads();
        if (tid < rc) {
            const int i = rlist[tid];
            const int c = sidx[i];
            const float4* bp = (const float4*)(g_Yf + (size_t)c * KT);
            const float4* ap = (const float4*)sYr;
            float acc = 0.f;
            for (int k = 0; k < KT / 4; ++k) {
                const float4 a = ap[k];
                const float4 b = __ldg(bp + k);
                acc = fmaf(a.x, b.x, acc);
                acc = fmaf(a.y, b.y, acc);
                acc = fmaf(a.z, b.z, acc);
                acc = fmaf(a.w, b.w, acc);
            }
            sex[tid] = acc;
        }
        __syncthreads();
        if (tid < rc) sval[rlist[tid]] = sex[tid];
        __syncthreads();
    }

    // final rank + scatter
    for (int i = tid; i < cnt; i += 256) {
        const float vi = sval[i];
        if (vi <= EPSILON) continue;
        const int ii = sidx[i];
        int rank = 0;
        for (int j = 0; j < cnt; ++j) {
            const float vj = sval[j];
            if (vj <= EPSILON) continue;
            rank += (vj > vi) || (vj == vi && sidx[j] < ii);
        }
        if (rank < TOPK) r[ii] = vi;
    }
}

// ---------------------------------------------------------------------------
extern "C" void kernel_launch(void* const* d_in, const int* in_sizes, int n_in,
                              void* d_out, int out_size)
{
    const float* x = (const float*)d_in[0];
    const float* w = (const float*)d_in[1];
    if (n_in >= 2 && in_sizes[0] == PP * DD) { const float* t = x; x = w; w = t; }
    float* C = (float*)d_out;

    cudaFuncSetAttribute(syrk_mma_kernel,
                         cudaFuncAttributeMaxDynamicSharedMemorySize, SMEM_TOTAL);
    cudaFuncSetAttribute(topk_kernel,
                         cudaFuncAttributeMaxDynamicSharedMemorySize, KT * sizeof(float));

    build_y_kernel<<<NN, 256>>>(x, w);
    dim3 grid(32, 64);
    syrk_mma_kernel<<<grid, 256, SMEM_TOTAL>>>(C);
    topk_kernel<<<NN, 256, KT * sizeof(float)>>>(C);
}